// round 3
// baseline (speedup 1.0000x reference)
#include <cuda_runtime.h>
#include <math.h>
#include <stdint.h>

// SSIM loss, separable 11-tap Gaussian.
// V-first separable conv: vertical pass packed over x (fma.rn.f32x2, natively
// aligned pairs, no transpose), horizontal pass scalar with perfect per-thread
// load balance and conflict-free LDS.128 (float4-interleaved arrays, pitch 77).
// 4 convolutions: m1=conv(p), m2=conv(t), S=conv(p^2+t^2), X=conv(p*t).

#define KW      11
#define HALO    5
#define TILE_X  64
#define TILE_Y  32
#define IN_W    74                 // TILE_X + 2*HALO
#define IN_H    42                 // TILE_Y + 2*HALO
#define IP      76                 // input row pitch (floats), even for LDS.64
#define NXP     37                 // x-pairs (74/2)
#define VP      77                 // V-output row pitch in float4 (odd -> conflict-free)
#define IMG     512
#define NCHAN   48
#define NT      256

#define C1F 1.0e-4f
#define C2F 9.0e-4f

// smem: sp[42*76] | st[42*76] | vout float4[32*77]
#define SP_OFF   0
#define ST_OFF   (IN_H * IP)                   // 3192 floats
#define VO_OFF   (2 * IN_H * IP)               // 6384 floats (byte 25536, 16B aligned)
#define SMEM_BYTES ((2 * IN_H * IP) * 4 + TILE_Y * VP * 16)   // 25536 + 39424 = 64960

__device__ double g_accum;    // zeroed at module load; finalize self-resets

// ---------------- packed f32x2 helpers ----------------
__device__ __forceinline__ uint64_t pk2(float x, float y) {
    uint64_t r; asm("mov.b64 %0, {%1, %2};" : "=l"(r) : "f"(x), "f"(y)); return r;
}
__device__ __forceinline__ float2 up2(uint64_t v) {
    float2 r; asm("mov.b64 {%0, %1}, %2;" : "=f"(r.x), "=f"(r.y) : "l"(v)); return r;
}
__device__ __forceinline__ uint64_t fma2(uint64_t a, uint64_t b, uint64_t c) {
    uint64_t d; asm("fma.rn.f32x2 %0, %1, %2, %3;" : "=l"(d) : "l"(a), "l"(b), "l"(c)); return d;
}
__device__ __forceinline__ uint64_t mul2(uint64_t a, uint64_t b) {
    uint64_t d; asm("mul.rn.f32x2 %0, %1, %2;" : "=l"(d) : "l"(a), "l"(b)); return d;
}

__global__ void __launch_bounds__(NT, 3) ssim_kernel(
    const float* __restrict__ pred,
    const float* __restrict__ target,
    const float* __restrict__ window)
{
    extern __shared__ float smem[];
    __shared__ float sg[KW];
    __shared__ float warp_sums[NT / 32];

    float*  sp = smem + SP_OFF;
    float*  st = smem + ST_OFF;
    float4* vo = reinterpret_cast<float4*>(smem + VO_OFF);

    const int tid = threadIdx.x;

    // 1D taps from the 2D outer-product window diagonal: g[i] = sqrt(w[i][i])
    if (tid < KW) sg[tid] = sqrtf(window[tid * KW + tid]);

    // ---- load 42x74 halo tile (zero padded) ----
    const int gx0 = blockIdx.x * TILE_X - HALO;
    const int gy0 = blockIdx.y * TILE_Y - HALO;
    const size_t plane = (size_t)blockIdx.z * (IMG * IMG);
    const float* __restrict__ pb = pred + plane;
    const float* __restrict__ tb = target + plane;

    for (int i = tid; i < IN_H * IN_W; i += NT) {
        int y = i / IN_W, x = i - y * IN_W;
        int gx = gx0 + x, gy = gy0 + y;
        float p = 0.f, t = 0.f;
        if ((unsigned)gx < IMG && (unsigned)gy < IMG) {
            int off = gy * IMG + gx;
            p = pb[off];
            t = tb[off];
        }
        sp[y * IP + x] = p;
        st[y * IP + x] = t;
    }
    __syncthreads();

    // packed taps
    uint64_t wk2[KW];
    #pragma unroll
    for (int k = 0; k < KW; k++) wk2[k] = pk2(sg[k], sg[k]);

    // ========== pass 1: vertical conv, packed over x ==========
    // item = (y out-row 0..31, xp 0..36). 1184 items, fine-grained (8% tail).
    for (int id = tid; id < TILE_Y * NXP; id += NT) {
        int y  = id / NXP;
        int xp = id - y * NXP;
        const float* pp = sp + y * IP + 2 * xp;
        const float* tp = st + y * IP + 2 * xp;

        uint64_t m1 = 0, m2 = 0, S = 0, X = 0;
        #pragma unroll
        for (int k = 0; k < KW; k++) {
            uint64_t p = *reinterpret_cast<const uint64_t*>(pp + k * IP);
            uint64_t t = *reinterpret_cast<const uint64_t*>(tp + k * IP);
            uint64_t x  = mul2(p, t);
            uint64_t s  = fma2(p, p, mul2(t, t));
            uint64_t w  = wk2[k];
            m1 = fma2(w, p, m1);
            m2 = fma2(w, t, m2);
            S  = fma2(w, s, S);
            X  = fma2(w, x, X);
        }
        float2 a = up2(m1), b = up2(m2), c = up2(S), d = up2(X);
        int o = y * VP + 2 * xp;
        vo[o]     = make_float4(a.x, b.x, c.x, d.x);
        vo[o + 1] = make_float4(a.y, b.y, c.y, d.y);
    }
    __syncthreads();

    // ========== pass 2: horizontal conv, scalar, 1 item/thread ==========
    // lane = y (0..31), warp id = x-group (8 outputs each). Conflict-free LDS.128.
    const int y  = tid & 31;
    const int xg = tid >> 5;
    const float4* vrow = vo + y * VP + xg * 8;

    float g[KW];
    #pragma unroll
    for (int k = 0; k < KW; k++) g[k] = sg[k];

    float am1[8], am2[8], aS[8], aX[8];
    #pragma unroll
    for (int o = 0; o < 8; o++) { am1[o] = 0.f; am2[o] = 0.f; aS[o] = 0.f; aX[o] = 0.f; }

    #pragma unroll
    for (int k = 0; k < KW + 7; k++) {
        float4 v = vrow[k];
        #pragma unroll
        for (int o = 0; o < 8; o++) {
            int ki = k - o;
            if (ki >= 0 && ki < KW) {
                float w = g[ki];
                am1[o] = fmaf(w, v.x, am1[o]);
                am2[o] = fmaf(w, v.y, am2[o]);
                aS[o]  = fmaf(w, v.z, aS[o]);
                aX[o]  = fmaf(w, v.w, aX[o]);
            }
        }
    }

    // ---- SSIM map + accumulate ----
    float lsum = 0.f;
    #pragma unroll
    for (int o = 0; o < 8; o++) {
        float mu1 = am1[o], mu2 = am2[o];
        float mu1s = mu1 * mu1;
        float mu2s = mu2 * mu2;
        float mu12 = mu1 * mu2;
        float msum = mu1s + mu2s;
        float s12  = aX[o] - mu12;                 // sigma12
        float ssum = aS[o] - msum;                 // sigma1_sq + sigma2_sq
        float num  = (2.f * mu12 + C1F) * (2.f * s12 + C2F);
        float den  = (msum + C1F) * (ssum + C2F);
        lsum += __fdividef(num, den);
    }

    // ---- block reduce + global atomic ----
    #pragma unroll
    for (int off = 16; off > 0; off >>= 1)
        lsum += __shfl_down_sync(0xffffffffu, lsum, off);
    if ((tid & 31) == 0) warp_sums[tid >> 5] = lsum;
    __syncthreads();
    if (tid == 0) {
        float s = 0.f;
        #pragma unroll
        for (int i = 0; i < NT / 32; i++) s += warp_sums[i];
        atomicAdd(&g_accum, (double)s);
    }
}

__global__ void finalize_kernel(float* __restrict__ out) {
    const double n = (double)NCHAN * IMG * IMG;
    out[0] = (float)(1.0 - g_accum / n);
    g_accum = 0.0;    // self-reset for deterministic graph replays
}

extern "C" void kernel_launch(void* const* d_in, const int* in_sizes, int n_in,
                              void* d_out, int out_size)
{
    const float* pred   = (const float*)d_in[0];
    const float* target = (const float*)d_in[1];
    const float* window = (const float*)d_in[2];
    float* out = (float*)d_out;

    static bool attr_set = false;
    if (!attr_set) {
        cudaFuncSetAttribute(ssim_kernel, cudaFuncAttributeMaxDynamicSharedMemorySize, SMEM_BYTES);
        attr_set = true;
    }

    dim3 grid(IMG / TILE_X, IMG / TILE_Y, NCHAN);
    ssim_kernel<<<grid, NT, SMEM_BYTES>>>(pred, target, window);
    finalize_kernel<<<1, 1>>>(out);
}

// round 4
// speedup vs baseline: 1.2838x; 1.2838x over previous
#include <cuda_runtime.h>
#include <math.h>

// SSIM loss, separable 11-tap Gaussian, single fused kernel.
// H-first separable conv on 32x32 tiles (R1 structure), 4 convolutions only:
// m1=conv(p), m2=conv(t), S=conv(p^2+t^2), X=conv(p*t).
// Finalize fused via last-block ticket; bank-conflict-free smem layouts.

#define TILE  32
#define HALO  5
#define KW    11
#define TW    42                  // TILE + 2*HALO
#define IP    43                  // sp/st row pitch (floats); 43 % 32 = 11 (coprime)
#define VTP   33                  // vt row pitch (float4); 33 % 32 = 1
#define IMG   512
#define NCHAN 48
#define NT    256
#define NBLK  ((IMG/TILE)*(IMG/TILE)*NCHAN)   // 12288

#define C1F 1.0e-4f
#define C2F 9.0e-4f

__device__ double g_accum;        // zero at load; last block self-resets
__device__ unsigned int g_count;  // ticket counter; last block self-resets

__global__ void __launch_bounds__(NT, 4) ssim_kernel(
    const float* __restrict__ pred,
    const float* __restrict__ target,
    const float* __restrict__ window,
    float* __restrict__ out)
{
    __shared__ float  sp[TW * IP];
    __shared__ float  st[TW * IP];
    __shared__ float4 vt[TW * VTP];     // interleaved (m1, m2, S, X)
    __shared__ float  sg[KW];
    __shared__ float  warp_sums[NT / 32];

    const int tid = threadIdx.x;

    // 1D taps from the 2D outer-product window diagonal: g[i] = sqrt(w[i][i])
    if (tid < KW) sg[tid] = sqrtf(window[tid * KW + tid]);

    // ---- load 42x42 halo tile (zero padded) ----
    const int gx0 = blockIdx.x * TILE - HALO;
    const int gy0 = blockIdx.y * TILE - HALO;
    const size_t plane = (size_t)blockIdx.z * (IMG * IMG);
    const float* __restrict__ pb = pred + plane;
    const float* __restrict__ tb = target + plane;

    #pragma unroll
    for (int i = tid; i < TW * TW; i += NT) {
        int y = i / TW, x = i - y * TW;
        int gx = gx0 + x, gy = gy0 + y;
        float p = 0.f, t = 0.f;
        if ((unsigned)gx < IMG && (unsigned)gy < IMG) {
            int off = gy * IMG + gx;
            p = pb[off];
            t = tb[off];
        }
        sp[y * IP + x] = p;
        st[y * IP + x] = t;
    }
    __syncthreads();

    float g[KW];
    #pragma unroll
    for (int k = 0; k < KW; k++) g[k] = sg[k];

    // ========== pass 1: horizontal conv, 42 rows x 8 x-groups of 4 ==========
    // item id -> (xgi = id/42, row = id%42): consecutive lanes take consecutive
    // rows (bank step 11 on loads, step 1 on float4 stores -> conflict-free).
    for (int id = tid; id < 8 * TW; id += NT) {
        int xgi = id / TW;
        int row = id - xgi * TW;
        int xg  = xgi * 4;
        const float* pr = sp + row * IP + xg;
        const float* tr = st + row * IP + xg;

        float m1[4] = {0.f, 0.f, 0.f, 0.f};
        float m2[4] = {0.f, 0.f, 0.f, 0.f};
        float S [4] = {0.f, 0.f, 0.f, 0.f};
        float X [4] = {0.f, 0.f, 0.f, 0.f};

        #pragma unroll
        for (int k = 0; k < KW + 3; k++) {
            float p = pr[k];
            float t = tr[k];
            float x = p * t;
            float s = fmaf(p, p, t * t);
            #pragma unroll
            for (int o = 0; o < 4; o++) {
                int ki = k - o;
                if (ki >= 0 && ki < KW) {         // compile-time folded (full unroll)
                    float w = g[ki];
                    m1[o] = fmaf(w, p, m1[o]);
                    m2[o] = fmaf(w, t, m2[o]);
                    S [o] = fmaf(w, s, S [o]);
                    X [o] = fmaf(w, x, X [o]);
                }
            }
        }
        float4* vrow = vt + row * VTP + xg;
        #pragma unroll
        for (int o = 0; o < 4; o++)
            vrow[o] = make_float4(m1[o], m2[o], S[o], X[o]);
    }
    __syncthreads();

    // ========== pass 2: vertical conv, 1 column x 4 y-outputs per thread ==========
    const int tx    = tid & 31;
    const int ybase = (tid >> 5) << 2;
    const float4* vcol = vt + ybase * VTP + tx;

    float am1[4] = {0.f, 0.f, 0.f, 0.f};
    float am2[4] = {0.f, 0.f, 0.f, 0.f};
    float aS [4] = {0.f, 0.f, 0.f, 0.f};
    float aX [4] = {0.f, 0.f, 0.f, 0.f};

    #pragma unroll
    for (int k = 0; k < KW + 3; k++) {
        float4 v = vcol[k * VTP];
        #pragma unroll
        for (int o = 0; o < 4; o++) {
            int ki = k - o;
            if (ki >= 0 && ki < KW) {
                float w = g[ki];
                am1[o] = fmaf(w, v.x, am1[o]);
                am2[o] = fmaf(w, v.y, am2[o]);
                aS [o] = fmaf(w, v.z, aS [o]);
                aX [o] = fmaf(w, v.w, aX [o]);
            }
        }
    }

    // ---- SSIM map + accumulate ----
    float lsum = 0.f;
    #pragma unroll
    for (int o = 0; o < 4; o++) {
        float mu1  = am1[o], mu2 = am2[o];
        float mu1s = mu1 * mu1;
        float mu2s = mu2 * mu2;
        float mu12 = mu1 * mu2;
        float msum = mu1s + mu2s;
        float s12  = aX[o] - mu12;                 // sigma12
        float ssum = aS[o] - msum;                 // sigma1_sq + sigma2_sq
        float num  = (2.f * mu12 + C1F) * (2.f * s12 + C2F);
        float den  = (msum + C1F) * (ssum + C2F);
        lsum += __fdividef(num, den);
    }

    // ---- block reduce ----
    #pragma unroll
    for (int off = 16; off > 0; off >>= 1)
        lsum += __shfl_down_sync(0xffffffffu, lsum, off);
    if ((tid & 31) == 0) warp_sums[tid >> 5] = lsum;
    __syncthreads();

    // ---- fused finalize: last block writes the scalar and resets state ----
    if (tid == 0) {
        float s = 0.f;
        #pragma unroll
        for (int i = 0; i < NT / 32; i++) s += warp_sums[i];
        atomicAdd(&g_accum, (double)s);
        __threadfence();
        unsigned int ticket = atomicAdd(&g_count, 1u);
        if (ticket == NBLK - 1) {
            double total = atomicAdd(&g_accum, 0.0);
            const double n = (double)NCHAN * IMG * IMG;
            out[0] = (float)(1.0 - total / n);
            g_accum = 0.0;        // reset for next graph replay
            g_count = 0u;
        }
    }
}

extern "C" void kernel_launch(void* const* d_in, const int* in_sizes, int n_in,
                              void* d_out, int out_size)
{
    const float* pred   = (const float*)d_in[0];
    const float* target = (const float*)d_in[1];
    const float* window = (const float*)d_in[2];
    float* out = (float*)d_out;

    dim3 grid(IMG / TILE, IMG / TILE, NCHAN);
    ssim_kernel<<<grid, NT>>>(pred, target, window, out);
}